// round 5
// baseline (speedup 1.0000x reference)
#include <cuda_runtime.h>

#define NN 100000
#define EE 1200000
#define GG 128
#define HH 64

// ---------------- static device buffers (no allocation allowed) ----------------
__device__ int g_deg[NN + 1];
__device__ int g_row[NN + 1];
__device__ int g_cur[NN + 1];
__device__ int g_src[EE];
__device__ int g_bsums[256];
__device__ int g_cntg[GG];
__device__ int g_e64, g_b64;
__device__ float g_Q[(size_t)NN * HH];
__device__ float g_K[(size_t)NN * HH];
__device__ float g_V[(size_t)NN * HH];
__device__ float g_S[(size_t)NN * HH];
__device__ float g_h1[(size_t)NN * HH];
__device__ float g_h2[(size_t)NN * HH];

// ---------------- helpers ----------------
__device__ __forceinline__ unsigned long long pack2(float a, float b) {
    unsigned long long r;
    asm("mov.b64 %0, {%1, %2};" : "=l"(r) : "r"(__float_as_uint(a)), "r"(__float_as_uint(b)));
    return r;
}
__device__ __forceinline__ void unpack2(unsigned long long v, float& a, float& b) {
    unsigned int lo, hi;
    asm("mov.b64 {%0, %1}, %2;" : "=r"(lo), "=r"(hi) : "l"(v));
    a = __uint_as_float(lo);
    b = __uint_as_float(hi);
}
__device__ __forceinline__ unsigned long long ffma2(unsigned long long a, unsigned long long b,
                                                    unsigned long long c) {
    unsigned long long d;
    asm("fma.rn.f32x2 %0, %1, %2, %3;" : "=l"(d) : "l"(a), "l"(b), "l"(c));
    return d;
}
__device__ __forceinline__ int ld_idx(const void* p, long long i, int is64) {
    if (is64) return (int)((const long long*)p)[i];
    return ((const int*)p)[i];
}

// ---------------- dtype detection (int32 vs int64 indices) ----------------
__global__ void detect_kernel(const void* ei, const void* bids, int E, int N) {
    const int* p = (const int*)ei;
    int nz = 0;
    for (int k = 1; k < 129; k += 2) nz += (p[k] != 0);
    g_e64 = (nz <= 4) ? 1 : 0;
    const int* q = (const int*)bids;
    int nz2 = 0;
    int st = N - 63;
    if (!(st & 1)) st++;
    for (int k = st; k < N; k += 2) nz2 += (q[k] != 0);
    g_b64 = (nz2 <= 4) ? 1 : 0;
}

// ---------------- CSR build ----------------
__global__ void zero_kernel() {
    int i = blockIdx.x * blockDim.x + threadIdx.x;
    if (i < NN + 1) g_deg[i] = 0;
    if (i < GG) g_cntg[i] = 0;
}

__global__ void hist_edges_kernel(const void* ei, int E) {
    int e = blockIdx.x * blockDim.x + threadIdx.x;
    if (e >= E) return;
    int is64 = g_e64;
    int dst = ld_idx(ei, (long long)E + e, is64);
    atomicAdd(&g_deg[dst], 1);
}

__global__ void batch_hist_kernel(const void* bids, int N) {
    int tid = blockIdx.x * blockDim.x + threadIdx.x;
    long long i0 = (long long)tid * 8;
    if (i0 >= N) return;
    int is64 = g_b64;
    long long lim = i0 + 8;
    if (lim > N) lim = N;
    int prev = ld_idx(bids, i0, is64);
    int run = 1;
    for (long long i = i0 + 1; i < lim; i++) {
        int b = ld_idx(bids, i, is64);
        if (b == prev)
            run++;
        else {
            atomicAdd(&g_cntg[prev], run);
            prev = b;
            run = 1;
        }
    }
    atomicAdd(&g_cntg[prev], run);
}

__global__ void scan1_kernel(int n) {
    __shared__ int wsum[32];
    int tid = threadIdx.x, lane = tid & 31, wid = tid >> 5;
    int i = blockIdx.x * 1024 + tid;
    int v = (i < n) ? g_deg[i] : 0;
#pragma unroll
    for (int d = 1; d < 32; d <<= 1) {
        int t = __shfl_up_sync(0xffffffffu, v, d);
        if (lane >= d) v += t;
    }
    if (lane == 31) wsum[wid] = v;
    __syncthreads();
    if (wid == 0) {
        int x = wsum[lane];
#pragma unroll
        for (int d = 1; d < 32; d <<= 1) {
            int t = __shfl_up_sync(0xffffffffu, x, d);
            if (lane >= d) x += t;
        }
        wsum[lane] = x;
    }
    __syncthreads();
    if (wid > 0) v += wsum[wid - 1];
    if (i < n) g_row[i + 1] = v;
    if (tid == 1023) g_bsums[blockIdx.x] = wsum[31];
}

// merged: per-block exclusive prefix over bsums + apply (kills serial scan2)
__global__ void scan23_kernel(int n, int nb) {
    __shared__ int sh[128];
    int t = threadIdx.x;
    if (t < 128) sh[t] = (t < nb && t < blockIdx.x) ? g_bsums[t] : 0;
    __syncthreads();
    for (int s = 64; s > 0; s >>= 1) {
        if (t < s) sh[t] += sh[t + s];
        __syncthreads();
    }
    int off = sh[0];
    int i = blockIdx.x * 1024 + t;
    if (i < n) {
        int val = g_row[i + 1] + off;
        g_row[i + 1] = val;
        g_cur[i + 1] = val;
    }
    if (blockIdx.x == 0 && t == 0) {
        g_row[0] = 0;
        g_cur[0] = 0;
    }
}

__global__ void fill_kernel(const void* ei, int E) {
    int e = blockIdx.x * blockDim.x + threadIdx.x;
    if (e >= E) return;
    int is64 = g_e64;
    int src = ld_idx(ei, e, is64);
    int dst = ld_idx(ei, (long long)E + e, is64);
    int pos = atomicAdd(&g_cur[dst], 1);
    g_src[pos] = src;
}

// ---------------- input projection (FIN=16): 256 threads ----------------
__global__ void __launch_bounds__(256) proj16_kernel(const float* __restrict__ hin,
                                                     const float* __restrict__ Wq, const float* __restrict__ bq,
                                                     const float* __restrict__ Wk, const float* __restrict__ bk,
                                                     const float* __restrict__ Wv, const float* __restrict__ bv,
                                                     const float* __restrict__ Ws, const float* __restrict__ bs,
                                                     int nN) {
    const int FIN = 16;
    __shared__ __align__(16) float xsh[FIN * 36];
    int t = threadIdx.x;
    int col = t & 63;
    int sel = t >> 6;
    const float* W;
    const float* B;
    float* O;
    if (sel == 0) { W = Wq; B = bq; O = g_Q; }
    else if (sel == 1) { W = Wk; B = bk; O = g_K; }
    else if (sel == 2) { W = Wv; B = bv; O = g_V; }
    else { W = Ws; B = bs; O = g_S; }

    unsigned long long wp[FIN];
#pragma unroll
    for (int j = 0; j < FIN; j++) {
        float w = W[j * 64 + col];
        wp[j] = pack2(w, w);
    }
    float bb = B[col];
    unsigned long long bp = pack2(bb, bb);

    int base = blockIdx.x * 32;
    int cnt = nN - base;
    if (cnt > 32) cnt = 32;
    int total = cnt * FIN;
    for (int idx = t; idx < total; idx += 256) {
        int nd = idx / FIN;
        int j = idx - nd * FIN;
        xsh[j * 36 + nd] = hin[(long long)base * FIN + idx];
    }
    __syncthreads();

    for (int p = 0; p < 32; p += 8) {
        unsigned long long a0 = bp, a1 = bp, a2 = bp, a3 = bp;
#pragma unroll
        for (int j = 0; j < FIN; j++) {
            ulonglong2 x01 = *reinterpret_cast<const ulonglong2*>(&xsh[j * 36 + p]);
            ulonglong2 x23 = *reinterpret_cast<const ulonglong2*>(&xsh[j * 36 + p + 4]);
            a0 = ffma2(x01.x, wp[j], a0);
            a1 = ffma2(x01.y, wp[j], a1);
            a2 = ffma2(x23.x, wp[j], a2);
            a3 = ffma2(x23.y, wp[j], a3);
        }
        float f[8];
        unpack2(a0, f[0], f[1]);
        unpack2(a1, f[2], f[3]);
        unpack2(a2, f[4], f[5]);
        unpack2(a3, f[6], f[7]);
#pragma unroll
        for (int u = 0; u < 8; u++)
            if (p + u < cnt) O[(long long)(base + p + u) * 64 + col] = f[u];
    }
}

// ---------------- hidden projection (FIN=64): 512 threads, split-j, smem combine ----------------
__global__ void __launch_bounds__(512) proj64_kernel(const float* __restrict__ hin,
                                                     const float* __restrict__ Wq, const float* __restrict__ bq,
                                                     const float* __restrict__ Wk, const float* __restrict__ bk,
                                                     const float* __restrict__ Wv, const float* __restrict__ bv,
                                                     const float* __restrict__ Ws, const float* __restrict__ bs,
                                                     int nN) {
    __shared__ __align__(16) float xsh[64 * 36];       // 9216 floats, transposed tile
    __shared__ float comb[2][4][8][64];                // double-buffered partial sums
    int t = threadIdx.x;
    int col = t & 63;
    int jh = (t >> 6) & 1;     // which half of j-range
    int sel = t >> 7;          // matrix: 0=Q 1=K 2=V 3=S
    const float* W;
    const float* B;
    float* O;
    if (sel == 0) { W = Wq; B = bq; O = g_Q; }
    else if (sel == 1) { W = Wk; B = bk; O = g_K; }
    else if (sel == 2) { W = Wv; B = bv; O = g_V; }
    else { W = Ws; B = bs; O = g_S; }

    unsigned long long wp[32];
#pragma unroll
    for (int jj = 0; jj < 32; jj++) {
        float w = W[(jh * 32 + jj) * 64 + col];
        wp[jj] = pack2(w, w);
    }
    unsigned long long bp = 0;
    if (jh == 0) {
        float bb = B[col];
        bp = pack2(bb, bb);
    }

    int base = blockIdx.x * 32;
    int cnt = nN - base;
    if (cnt > 32) cnt = 32;
    int total = cnt * 64;
    for (int idx = t; idx < total; idx += 512) {
        int nd = idx >> 6;
        int j = idx & 63;
        xsh[j * 36 + nd] = hin[(long long)base * 64 + idx];
    }
    __syncthreads();

    const float* xb = &xsh[jh * 32 * 36];
    for (int p = 0; p < 32; p += 8) {
        int buf = (p >> 3) & 1;
        unsigned long long a0 = bp, a1 = bp, a2 = bp, a3 = bp;
#pragma unroll
        for (int jj = 0; jj < 32; jj++) {
            ulonglong2 x01 = *reinterpret_cast<const ulonglong2*>(&xb[jj * 36 + p]);
            ulonglong2 x23 = *reinterpret_cast<const ulonglong2*>(&xb[jj * 36 + p + 4]);
            a0 = ffma2(x01.x, wp[jj], a0);
            a1 = ffma2(x01.y, wp[jj], a1);
            a2 = ffma2(x23.x, wp[jj], a2);
            a3 = ffma2(x23.y, wp[jj], a3);
        }
        float f[8];
        unpack2(a0, f[0], f[1]);
        unpack2(a1, f[2], f[3]);
        unpack2(a2, f[4], f[5]);
        unpack2(a3, f[6], f[7]);
        if (jh == 1) {
#pragma unroll
            for (int u = 0; u < 8; u++) comb[buf][sel][u][col] = f[u];
        }
        __syncthreads();
        if (jh == 0) {
#pragma unroll
            for (int u = 0; u < 8; u++) {
                float r = f[u] + comb[buf][sel][u][col];
                if (p + u < cnt) O[(long long)(base + p + u) * 64 + col] = r;
            }
        }
    }
}

// ---------------- attention: 4 edges/warp, 8 lanes/edge, split online softmax ----------------
__global__ void __launch_bounds__(256) attn_kernel(float* __restrict__ hout, int nN) {
    int node = (blockIdx.x << 3) + (threadIdx.x >> 5);
    if (node >= nN) return;
    int lane = threadIdx.x & 31;
    int sub = lane >> 3;   // which edge of the quad (0..3)
    int sl = lane & 7;     // dim group: dims 8sl..8sl+7
    const float4* Qp = reinterpret_cast<const float4*>(&g_Q[(long long)node * 64 + 8 * sl]);
    float4 qa = Qp[0], qb = Qp[1];
    qa.x *= 0.125f; qa.y *= 0.125f; qa.z *= 0.125f; qa.w *= 0.125f;  // 1/sqrt(64)
    qb.x *= 0.125f; qb.y *= 0.125f; qb.z *= 0.125f; qb.w *= 0.125f;
    int start = g_row[node], end = g_row[node + 1];
    float m = -1e30f, s = 0.f;
    float4 aa = {0.f, 0.f, 0.f, 0.f}, ab = {0.f, 0.f, 0.f, 0.f};
    for (int e = start; e < end; e += 4) {
        int ee = e + sub;
        bool act = ee < end;
        int cur = act ? __ldg(&g_src[ee]) : 0;
        const float4* Kp = reinterpret_cast<const float4*>(&g_K[(long long)cur * 64 + 8 * sl]);
        const float4* Vp = reinterpret_cast<const float4*>(&g_V[(long long)cur * 64 + 8 * sl]);
        float4 ka = Kp[0], kb = Kp[1];
        float4 va = Vp[0], vb = Vp[1];
        float pdot = qa.x * ka.x + qa.y * ka.y + qa.z * ka.z + qa.w * ka.w +
                     qb.x * kb.x + qb.y * kb.y + qb.z * kb.z + qb.w * kb.w;
        pdot += __shfl_xor_sync(0xffffffffu, pdot, 4);
        pdot += __shfl_xor_sync(0xffffffffu, pdot, 2);
        pdot += __shfl_xor_sync(0xffffffffu, pdot, 1);
        if (!act) pdot = -1e30f;
        float mn = fmaxf(m, pdot);
        float cs = __expf(m - mn);
        float w = act ? __expf(pdot - mn) : 0.f;
        s = s * cs + w;
        aa.x = aa.x * cs + w * va.x;
        aa.y = aa.y * cs + w * va.y;
        aa.z = aa.z * cs + w * va.z;
        aa.w = aa.w * cs + w * va.w;
        ab.x = ab.x * cs + w * vb.x;
        ab.y = ab.y * cs + w * vb.y;
        ab.z = ab.z * cs + w * vb.z;
        ab.w = ab.w * cs + w * vb.w;
        m = mn;
    }
    // merge 4 streams (exact in fp32): xor 8, then xor 16
#pragma unroll
    for (int off = 8; off <= 16; off <<= 1) {
        float m2 = __shfl_xor_sync(0xffffffffu, m, off);
        float s2 = __shfl_xor_sync(0xffffffffu, s, off);
        float t0 = __shfl_xor_sync(0xffffffffu, aa.x, off);
        float t1 = __shfl_xor_sync(0xffffffffu, aa.y, off);
        float t2 = __shfl_xor_sync(0xffffffffu, aa.z, off);
        float t3 = __shfl_xor_sync(0xffffffffu, aa.w, off);
        float t4 = __shfl_xor_sync(0xffffffffu, ab.x, off);
        float t5 = __shfl_xor_sync(0xffffffffu, ab.y, off);
        float t6 = __shfl_xor_sync(0xffffffffu, ab.z, off);
        float t7 = __shfl_xor_sync(0xffffffffu, ab.w, off);
        float M = fmaxf(m, m2);
        float c1 = __expf(m - M);
        float c2 = __expf(m2 - M);
        s = s * c1 + s2 * c2;
        aa.x = aa.x * c1 + t0 * c2;
        aa.y = aa.y * c1 + t1 * c2;
        aa.z = aa.z * c1 + t2 * c2;
        aa.w = aa.w * c1 + t3 * c2;
        ab.x = ab.x * c1 + t4 * c2;
        ab.y = ab.y * c1 + t5 * c2;
        ab.z = ab.z * c1 + t6 * c2;
        ab.w = ab.w * c1 + t7 * c2;
        m = M;
    }
    float inv = 1.f / (s + 1e-16f);
    if (sub == 0) {
        const float4* Sp = reinterpret_cast<const float4*>(&g_S[(long long)node * 64 + 8 * sl]);
        float4 s0 = Sp[0], s1 = Sp[1];
        float4 o0, o1;
        o0.x = aa.x * inv + s0.x;
        o0.y = aa.y * inv + s0.y;
        o0.z = aa.z * inv + s0.z;
        o0.w = aa.w * inv + s0.w;
        o1.x = ab.x * inv + s1.x;
        o1.y = ab.y * inv + s1.y;
        o1.z = ab.z * inv + s1.z;
        o1.w = ab.w * inv + s1.w;
        float4* Op = reinterpret_cast<float4*>(&hout[(long long)node * 64 + 8 * sl]);
        Op[0] = o0;
        Op[1] = o1;
    }
}

// ---------------- mean pool per graph + final linear ----------------
__global__ void __launch_bounds__(256) pool_kernel(const float* __restrict__ h,
                                                   const float* __restrict__ Wf,
                                                   const float* __restrict__ bf,
                                                   float* __restrict__ out) {
    __shared__ int ired[256];
    __shared__ float fred[256];
    __shared__ float pooled[64];
    int g = blockIdx.x, t = threadIdx.x;
    ired[t] = (t < g) ? g_cntg[t] : 0;
    __syncthreads();
    for (int sft = 128; sft > 0; sft >>= 1) {
        if (t < sft) ired[t] += ired[t + sft];
        __syncthreads();
    }
    int start = ired[0];
    int cntv = g_cntg[g];
    int dim = t & 63, qd = t >> 6;
    float loc = 0.f;
    for (int i = start + qd; i < start + cntv; i += 4) loc += h[(long long)i * 64 + dim];
    fred[t] = loc;
    __syncthreads();
    if (t < 64)
        pooled[t] = (fred[t] + fred[t + 64] + fred[t + 128] + fred[t + 192]) /
                    fmaxf((float)cntv, 1.f);
    __syncthreads();
    if (t < 5) {
        float acc = bf[t];
#pragma unroll
        for (int d = 0; d < 64; d++) acc += pooled[d] * Wf[d * 5 + t];
        out[g * 5 + t] = acc;
    }
}

// ---------------- launch ----------------
extern "C" void kernel_launch(void* const* d_in, const int* in_sizes, int n_in,
                              void* d_out, int out_size) {
    const float* x = (const float*)d_in[0];
    const void* ei = d_in[1];
    const void* bids = d_in[2];
    const float* Wq0 = (const float*)d_in[3];
    const float* bq0 = (const float*)d_in[4];
    const float* Wk0 = (const float*)d_in[5];
    const float* bk0 = (const float*)d_in[6];
    const float* Wv0 = (const float*)d_in[7];
    const float* bv0 = (const float*)d_in[8];
    const float* Ws0 = (const float*)d_in[9];
    const float* bs0 = (const float*)d_in[10];
    const float* Wqh = (const float*)d_in[11];
    const float* bqh = (const float*)d_in[12];
    const float* Wkh = (const float*)d_in[13];
    const float* bkh = (const float*)d_in[14];
    const float* Wvh = (const float*)d_in[15];
    const float* bvh = (const float*)d_in[16];
    const float* Wsh = (const float*)d_in[17];
    const float* bsh = (const float*)d_in[18];
    const float* Wf = (const float*)d_in[19];
    const float* bf = (const float*)d_in[20];
    float* out = (float*)d_out;

    int N = in_sizes[0] / 16;  // 100000
    int E = in_sizes[1] / 2;   // 1200000

    float *h1, *h2;
    cudaGetSymbolAddress((void**)&h1, g_h1);
    cudaGetSymbolAddress((void**)&h2, g_h2);

    int proj_grid = (N + 31) / 32;
    int attn_grid = (N + 7) / 8;
    int nb1 = (N + 1023) / 1024;

    // prep interleaved so proj16 lands at launch index 3 (ncu capture slot)
    detect_kernel<<<1, 1>>>(ei, bids, E, N);
    zero_kernel<<<(NN + 256) / 256, 256>>>();
    hist_edges_kernel<<<(E + 255) / 256, 256>>>(ei, E);
    proj16_kernel<<<proj_grid, 256>>>(x, Wq0, bq0, Wk0, bk0, Wv0, bv0, Ws0, bs0, N);
    scan1_kernel<<<nb1, 1024>>>(N);
    scan23_kernel<<<nb1, 1024>>>(N, nb1);
    fill_kernel<<<(E + 255) / 256, 256>>>(ei, E);
    batch_hist_kernel<<<((N + 7) / 8 + 255) / 256, 256>>>(bids, N);

    // layer 0 aggregation
    attn_kernel<<<attn_grid, 256>>>(h1, N);

    // hidden layers
    const float* hin = h1;
    float* hout = h2;
    for (int i = 0; i < 3; i++) {
        proj64_kernel<<<proj_grid, 512>>>(hin, Wqh + (size_t)i * 4096, bqh + (size_t)i * 64,
                                          Wkh + (size_t)i * 4096, bkh + (size_t)i * 64,
                                          Wvh + (size_t)i * 4096, bvh + (size_t)i * 64,
                                          Wsh + (size_t)i * 4096, bsh + (size_t)i * 64, N);
        attn_kernel<<<attn_grid, 256>>>(hout, N);
        const float* tmp = hin;
        hin = hout;
        hout = (float*)tmp;
    }

    // pool + head
    pool_kernel<<<GG, 256>>>(hin, Wf, bf, out);
}

// round 6
// speedup vs baseline: 1.1540x; 1.1540x over previous
#include <cuda_runtime.h>

#define NN 100000
#define EE 1200000
#define GG 128
#define HH 64

// ---------------- static device buffers (no allocation allowed) ----------------
__device__ int g_deg[NN + 1];
__device__ int g_row[NN + 1];
__device__ int g_cur[NN + 1];
__device__ int g_src[EE];
__device__ int g_bsums[256];
__device__ int g_cntg[GG];
__device__ int g_e64, g_b64;
__device__ float g_Q[(size_t)NN * HH];
__device__ float g_K[(size_t)NN * HH];
__device__ float g_V[(size_t)NN * HH];
__device__ float g_S[(size_t)NN * HH];
__device__ float g_h1[(size_t)NN * HH];
__device__ float g_h2[(size_t)NN * HH];

// ---------------- helpers ----------------
__device__ __forceinline__ unsigned long long pack2(float a, float b) {
    unsigned long long r;
    asm("mov.b64 %0, {%1, %2};" : "=l"(r) : "r"(__float_as_uint(a)), "r"(__float_as_uint(b)));
    return r;
}
__device__ __forceinline__ void unpack2(unsigned long long v, float& a, float& b) {
    unsigned int lo, hi;
    asm("mov.b64 {%0, %1}, %2;" : "=r"(lo), "=r"(hi) : "l"(v));
    a = __uint_as_float(lo);
    b = __uint_as_float(hi);
}
__device__ __forceinline__ unsigned long long ffma2(unsigned long long a, unsigned long long b,
                                                    unsigned long long c) {
    unsigned long long d;
    asm("fma.rn.f32x2 %0, %1, %2, %3;" : "=l"(d) : "l"(a), "l"(b), "l"(c));
    return d;
}
__device__ __forceinline__ int ld_idx(const void* p, long long i, int is64) {
    if (is64) return (int)((const long long*)p)[i];
    return ((const int*)p)[i];
}

// ---------------- dtype detection (int32 vs int64 indices) ----------------
__global__ void detect_kernel(const void* ei, const void* bids, int E, int N) {
    const int* p = (const int*)ei;
    int nz = 0;
    for (int k = 1; k < 129; k += 2) nz += (p[k] != 0);
    g_e64 = (nz <= 4) ? 1 : 0;
    const int* q = (const int*)bids;
    int nz2 = 0;
    int st = N - 63;
    if (!(st & 1)) st++;
    for (int k = st; k < N; k += 2) nz2 += (q[k] != 0);
    g_b64 = (nz2 <= 4) ? 1 : 0;
}

// ---------------- CSR build ----------------
__global__ void zero_kernel() {
    int i = blockIdx.x * blockDim.x + threadIdx.x;
    if (i < NN + 1) g_deg[i] = 0;
    if (i < GG) g_cntg[i] = 0;
}

__global__ void hist_edges_kernel(const void* ei, int E) {
    int e = blockIdx.x * blockDim.x + threadIdx.x;
    if (e >= E) return;
    int is64 = g_e64;
    int dst = ld_idx(ei, (long long)E + e, is64);
    atomicAdd(&g_deg[dst], 1);
}

__global__ void batch_hist_kernel(const void* bids, int N) {
    int tid = blockIdx.x * blockDim.x + threadIdx.x;
    long long i0 = (long long)tid * 8;
    if (i0 >= N) return;
    int is64 = g_b64;
    long long lim = i0 + 8;
    if (lim > N) lim = N;
    int prev = ld_idx(bids, i0, is64);
    int run = 1;
    for (long long i = i0 + 1; i < lim; i++) {
        int b = ld_idx(bids, i, is64);
        if (b == prev)
            run++;
        else {
            atomicAdd(&g_cntg[prev], run);
            prev = b;
            run = 1;
        }
    }
    atomicAdd(&g_cntg[prev], run);
}

__global__ void scan1_kernel(int n) {
    __shared__ int wsum[32];
    int tid = threadIdx.x, lane = tid & 31, wid = tid >> 5;
    int i = blockIdx.x * 1024 + tid;
    int v = (i < n) ? g_deg[i] : 0;
#pragma unroll
    for (int d = 1; d < 32; d <<= 1) {
        int t = __shfl_up_sync(0xffffffffu, v, d);
        if (lane >= d) v += t;
    }
    if (lane == 31) wsum[wid] = v;
    __syncthreads();
    if (wid == 0) {
        int x = wsum[lane];
#pragma unroll
        for (int d = 1; d < 32; d <<= 1) {
            int t = __shfl_up_sync(0xffffffffu, x, d);
            if (lane >= d) x += t;
        }
        wsum[lane] = x;
    }
    __syncthreads();
    if (wid > 0) v += wsum[wid - 1];
    if (i < n) g_row[i + 1] = v;
    if (tid == 1023) g_bsums[blockIdx.x] = wsum[31];
}

// merged: per-block reduction over preceding bsums + apply (no serial scan2)
__global__ void scan23_kernel(int n, int nb) {
    __shared__ int sh[128];
    int t = threadIdx.x;
    if (t < 128) sh[t] = (t < nb && t < blockIdx.x) ? g_bsums[t] : 0;
    __syncthreads();
    for (int s = 64; s > 0; s >>= 1) {
        if (t < s) sh[t] += sh[t + s];
        __syncthreads();
    }
    int off = sh[0];
    int i = blockIdx.x * 1024 + t;
    if (i < n) {
        int val = g_row[i + 1] + off;
        g_row[i + 1] = val;
        g_cur[i + 1] = val;
    }
    if (blockIdx.x == 0 && t == 0) {
        g_row[0] = 0;
        g_cur[0] = 0;
    }
}

__global__ void fill_kernel(const void* ei, int E) {
    int e = blockIdx.x * blockDim.x + threadIdx.x;
    if (e >= E) return;
    int is64 = g_e64;
    int src = ld_idx(ei, e, is64);
    int dst = ld_idx(ei, (long long)E + e, is64);
    int pos = atomicAdd(&g_cur[dst], 1);
    g_src[pos] = src;
}

// ---------------- input projection (FIN=16): 256 threads, 32-node tile (control) ----------------
__global__ void __launch_bounds__(256) proj16_kernel(const float* __restrict__ hin,
                                                     const float* __restrict__ Wq, const float* __restrict__ bq,
                                                     const float* __restrict__ Wk, const float* __restrict__ bk,
                                                     const float* __restrict__ Wv, const float* __restrict__ bv,
                                                     const float* __restrict__ Ws, const float* __restrict__ bs,
                                                     int nN) {
    const int FIN = 16;
    __shared__ __align__(16) float xsh[FIN * 36];
    int t = threadIdx.x;
    int col = t & 63;
    int sel = t >> 6;
    const float* W;
    const float* B;
    float* O;
    if (sel == 0) { W = Wq; B = bq; O = g_Q; }
    else if (sel == 1) { W = Wk; B = bk; O = g_K; }
    else if (sel == 2) { W = Wv; B = bv; O = g_V; }
    else { W = Ws; B = bs; O = g_S; }

    unsigned long long wp[FIN];
#pragma unroll
    for (int j = 0; j < FIN; j++) {
        float w = W[j * 64 + col];
        wp[j] = pack2(w, w);
    }
    float bb = B[col];
    unsigned long long bp = pack2(bb, bb);

    int base = blockIdx.x * 32;
    int cnt = nN - base;
    if (cnt > 32) cnt = 32;
    int total = cnt * FIN;
    for (int idx = t; idx < total; idx += 256) {
        int nd = idx / FIN;
        int j = idx - nd * FIN;
        xsh[j * 36 + nd] = hin[(long long)base * FIN + idx];
    }
    __syncthreads();

    for (int p = 0; p < 32; p += 8) {
        unsigned long long a0 = bp, a1 = bp, a2 = bp, a3 = bp;
#pragma unroll
        for (int j = 0; j < FIN; j++) {
            ulonglong2 x01 = *reinterpret_cast<const ulonglong2*>(&xsh[j * 36 + p]);
            ulonglong2 x23 = *reinterpret_cast<const ulonglong2*>(&xsh[j * 36 + p + 4]);
            a0 = ffma2(x01.x, wp[j], a0);
            a1 = ffma2(x01.y, wp[j], a1);
            a2 = ffma2(x23.x, wp[j], a2);
            a3 = ffma2(x23.y, wp[j], a3);
        }
        float f[8];
        unpack2(a0, f[0], f[1]);
        unpack2(a1, f[2], f[3]);
        unpack2(a2, f[4], f[5]);
        unpack2(a3, f[6], f[7]);
#pragma unroll
        for (int u = 0; u < 8; u++)
            if (p + u < cnt) O[(long long)(base + p + u) * 64 + col] = f[u];
    }
}

// ---------------- hidden projection (FIN=64): 256 threads, 64-node tile ----------------
__global__ void __launch_bounds__(256) proj64_kernel(const float* __restrict__ hin,
                                                     const float* __restrict__ Wq, const float* __restrict__ bq,
                                                     const float* __restrict__ Wk, const float* __restrict__ bk,
                                                     const float* __restrict__ Wv, const float* __restrict__ bv,
                                                     const float* __restrict__ Ws, const float* __restrict__ bs,
                                                     int nN) {
    const int FIN = 64;
    __shared__ __align__(16) float xsh[FIN * 68];  // transposed tile [j][node], stride 68
    int t = threadIdx.x;
    int col = t & 63;
    int sel = t >> 6;  // warp-uniform: 0=Q 1=K 2=V 3=S
    const float* W;
    const float* B;
    float* O;
    if (sel == 0) { W = Wq; B = bq; O = g_Q; }
    else if (sel == 1) { W = Wk; B = bk; O = g_K; }
    else if (sel == 2) { W = Wv; B = bv; O = g_V; }
    else { W = Ws; B = bs; O = g_S; }

    unsigned long long wp[FIN];
#pragma unroll
    for (int j = 0; j < FIN; j++) {
        float w = W[j * 64 + col];
        wp[j] = pack2(w, w);
    }
    float bb = B[col];
    unsigned long long bp = pack2(bb, bb);

    int base = blockIdx.x * 64;
    int cnt = nN - base;
    if (cnt > 64) cnt = 64;
    int total = cnt * FIN;
    for (int idx = t; idx < total; idx += 256) {
        int nd = idx >> 6;
        int j = idx & 63;
        xsh[j * 68 + nd] = hin[(long long)base * 64 + idx];
    }
    __syncthreads();

    for (int p = 0; p < 64; p += 8) {
        unsigned long long a0 = bp, a1 = bp, a2 = bp, a3 = bp;
#pragma unroll
        for (int j = 0; j < FIN; j++) {
            ulonglong2 x01 = *reinterpret_cast<const ulonglong2*>(&xsh[j * 68 + p]);
            ulonglong2 x23 = *reinterpret_cast<const ulonglong2*>(&xsh[j * 68 + p + 4]);
            a0 = ffma2(x01.x, wp[j], a0);
            a1 = ffma2(x01.y, wp[j], a1);
            a2 = ffma2(x23.x, wp[j], a2);
            a3 = ffma2(x23.y, wp[j], a3);
        }
        float f[8];
        unpack2(a0, f[0], f[1]);
        unpack2(a1, f[2], f[3]);
        unpack2(a2, f[4], f[5]);
        unpack2(a3, f[6], f[7]);
#pragma unroll
        for (int u = 0; u < 8; u++)
            if (p + u < cnt) O[(long long)(base + p + u) * 64 + col] = f[u];
    }
}

// ---------------- attention: 2 edges/warp, 16 lanes/edge (R4 known-good) ----------------
__global__ void __launch_bounds__(256) attn_kernel(float* __restrict__ hout, int nN) {
    int node = (blockIdx.x << 3) + (threadIdx.x >> 5);
    if (node >= nN) return;
    int lane = threadIdx.x & 31;
    int sub = lane >> 4;   // which edge of the pair
    int sl = lane & 15;    // dim group: dims 4sl..4sl+3
    float4 q4 = *reinterpret_cast<const float4*>(&g_Q[(long long)node * 64 + 4 * sl]);
    int start = g_row[node], end = g_row[node + 1];
    float m = -1e30f, s = 0.f;
    float4 a = {0.f, 0.f, 0.f, 0.f};
    for (int e = start; e < end; e += 2) {
        int ee = e + sub;
        bool act = ee < end;
        int cur = act ? __ldg(&g_src[ee]) : 0;
        float4 k4 = *reinterpret_cast<const float4*>(&g_K[(long long)cur * 64 + 4 * sl]);
        float4 v4 = *reinterpret_cast<const float4*>(&g_V[(long long)cur * 64 + 4 * sl]);
        float pdot = q4.x * k4.x + q4.y * k4.y + q4.z * k4.z + q4.w * k4.w;
#pragma unroll
        for (int off = 8; off; off >>= 1) pdot += __shfl_xor_sync(0xffffffffu, pdot, off);
        pdot *= 0.125f;  // 1/sqrt(64)
        if (!act) pdot = -1e30f;
        float mn = fmaxf(m, pdot);
        float cs = __expf(m - mn);
        float w = act ? __expf(pdot - mn) : 0.f;
        s = s * cs + w;
        a.x = a.x * cs + w * v4.x;
        a.y = a.y * cs + w * v4.y;
        a.z = a.z * cs + w * v4.z;
        a.w = a.w * cs + w * v4.w;
        m = mn;
    }
    // merge the two half-warp softmax streams (exact in fp32)
    float m2 = __shfl_xor_sync(0xffffffffu, m, 16);
    float s2 = __shfl_xor_sync(0xffffffffu, s, 16);
    float bx = __shfl_xor_sync(0xffffffffu, a.x, 16);
    float by = __shfl_xor_sync(0xffffffffu, a.y, 16);
    float bz = __shfl_xor_sync(0xffffffffu, a.z, 16);
    float bw = __shfl_xor_sync(0xffffffffu, a.w, 16);
    float M = fmaxf(m, m2);
    float c1 = __expf(m - M);
    float c2 = __expf(m2 - M);
    s = s * c1 + s2 * c2;
    a.x = a.x * c1 + bx * c2;
    a.y = a.y * c1 + by * c2;
    a.z = a.z * c1 + bz * c2;
    a.w = a.w * c1 + bw * c2;
    float inv = 1.f / (s + 1e-16f);
    if (sub == 0) {
        float4 sk = *reinterpret_cast<const float4*>(&g_S[(long long)node * 64 + 4 * sl]);
        float4 o;
        o.x = a.x * inv + sk.x;
        o.y = a.y * inv + sk.y;
        o.z = a.z * inv + sk.z;
        o.w = a.w * inv + sk.w;
        *reinterpret_cast<float4*>(&hout[(long long)node * 64 + 4 * sl]) = o;
    }
}

// ---------------- mean pool per graph + final linear ----------------
__global__ void __launch_bounds__(256) pool_kernel(const float* __restrict__ h,
                                                   const float* __restrict__ Wf,
                                                   const float* __restrict__ bf,
                                                   float* __restrict__ out) {
    __shared__ int ired[256];
    __shared__ float fred[256];
    __shared__ float pooled[64];
    int g = blockIdx.x, t = threadIdx.x;
    ired[t] = (t < g) ? g_cntg[t] : 0;
    __syncthreads();
    for (int sft = 128; sft > 0; sft >>= 1) {
        if (t < sft) ired[t] += ired[t + sft];
        __syncthreads();
    }
    int start = ired[0];
    int cntv = g_cntg[g];
    int dim = t & 63, qd = t >> 6;
    float loc = 0.f;
    for (int i = start + qd; i < start + cntv; i += 4) loc += h[(long long)i * 64 + dim];
    fred[t] = loc;
    __syncthreads();
    if (t < 64)
        pooled[t] = (fred[t] + fred[t + 64] + fred[t + 128] + fred[t + 192]) /
                    fmaxf((float)cntv, 1.f);
    __syncthreads();
    if (t < 5) {
        float acc = bf[t];
#pragma unroll
        for (int d = 0; d < 64; d++) acc += pooled[d] * Wf[d * 5 + t];
        out[g * 5 + t] = acc;
    }
}

// ---------------- launch ----------------
extern "C" void kernel_launch(void* const* d_in, const int* in_sizes, int n_in,
                              void* d_out, int out_size) {
    const float* x = (const float*)d_in[0];
    const void* ei = d_in[1];
    const void* bids = d_in[2];
    const float* Wq0 = (const float*)d_in[3];
    const float* bq0 = (const float*)d_in[4];
    const float* Wk0 = (const float*)d_in[5];
    const float* bk0 = (const float*)d_in[6];
    const float* Wv0 = (const float*)d_in[7];
    const float* bv0 = (const float*)d_in[8];
    const float* Ws0 = (const float*)d_in[9];
    const float* bs0 = (const float*)d_in[10];
    const float* Wqh = (const float*)d_in[11];
    const float* bqh = (const float*)d_in[12];
    const float* Wkh = (const float*)d_in[13];
    const float* bkh = (const float*)d_in[14];
    const float* Wvh = (const float*)d_in[15];
    const float* bvh = (const float*)d_in[16];
    const float* Wsh = (const float*)d_in[17];
    const float* bsh = (const float*)d_in[18];
    const float* Wf = (const float*)d_in[19];
    const float* bf = (const float*)d_in[20];
    float* out = (float*)d_out;

    int N = in_sizes[0] / 16;  // 100000
    int E = in_sizes[1] / 2;   // 1200000

    float *h1, *h2;
    cudaGetSymbolAddress((void**)&h1, g_h1);
    cudaGetSymbolAddress((void**)&h2, g_h2);

    int proj16_grid = (N + 31) / 32;
    int proj64_grid = (N + 63) / 64;
    int attn_grid = (N + 7) / 8;
    int nb1 = (N + 1023) / 1024;

    // prep; proj16 kept at launch slot 4 (ncu capture slot, control measurement)
    detect_kernel<<<1, 1>>>(ei, bids, E, N);
    zero_kernel<<<(NN + 256) / 256, 256>>>();
    hist_edges_kernel<<<(E + 255) / 256, 256>>>(ei, E);
    proj16_kernel<<<proj16_grid, 256>>>(x, Wq0, bq0, Wk0, bk0, Wv0, bv0, Ws0, bs0, N);
    scan1_kernel<<<nb1, 1024>>>(N);
    scan23_kernel<<<nb1, 1024>>>(N, nb1);
    fill_kernel<<<(E + 255) / 256, 256>>>(ei, E);
    batch_hist_kernel<<<((N + 7) / 8 + 255) / 256, 256>>>(bids, N);

    // layer 0 aggregation
    attn_kernel<<<attn_grid, 256>>>(h1, N);

    // hidden layers
    const float* hin = h1;
    float* hout = h2;
    for (int i = 0; i < 3; i++) {
        proj64_kernel<<<proj64_grid, 256>>>(hin, Wqh + (size_t)i * 4096, bqh + (size_t)i * 64,
                                            Wkh + (size_t)i * 4096, bkh + (size_t)i * 64,
                                            Wvh + (size_t)i * 4096, bvh + (size_t)i * 64,
                                            Wsh + (size_t)i * 4096, bsh + (size_t)i * 64, N);
        attn_kernel<<<attn_grid, 256>>>(hout, N);
        const float* tmp = hin;
        hin = hout;
        hout = (float*)tmp;
    }

    // pool + head
    pool_kernel<<<GG, 256>>>(hin, Wf, bf, out);
}

// round 7
// speedup vs baseline: 1.2730x; 1.1031x over previous
#include <cuda_runtime.h>

#define NN 100000
#define EE 1200000
#define GG 128
#define HH 64

// ---------------- static device buffers (no allocation allowed) ----------------
__device__ int g_deg[NN + 1];
__device__ int g_row[NN + 1];
__device__ int g_cur[NN + 1];
__device__ int g_src[EE];
__device__ int g_bsums[256];
__device__ int g_cntg[GG];
__device__ int g_e64, g_b64;
__device__ float g_Q[(size_t)NN * HH];
__device__ float g_K[(size_t)NN * HH];
__device__ float g_V[(size_t)NN * HH];
__device__ float g_S[(size_t)NN * HH];
__device__ float g_h1[(size_t)NN * HH];
__device__ float g_h2[(size_t)NN * HH];

// ---------------- helpers ----------------
__device__ __forceinline__ unsigned long long pack2(float a, float b) {
    unsigned long long r;
    asm("mov.b64 %0, {%1, %2};" : "=l"(r) : "r"(__float_as_uint(a)), "r"(__float_as_uint(b)));
    return r;
}
__device__ __forceinline__ void unpack2(unsigned long long v, float& a, float& b) {
    unsigned int lo, hi;
    asm("mov.b64 {%0, %1}, %2;" : "=r"(lo), "=r"(hi) : "l"(v));
    a = __uint_as_float(lo);
    b = __uint_as_float(hi);
}
__device__ __forceinline__ unsigned long long ffma2(unsigned long long a, unsigned long long b,
                                                    unsigned long long c) {
    unsigned long long d;
    asm("fma.rn.f32x2 %0, %1, %2, %3;" : "=l"(d) : "l"(a), "l"(b), "l"(c));
    return d;
}
__device__ __forceinline__ int ld_idx(const void* p, long long i, int is64) {
    if (is64) return (int)((const long long*)p)[i];
    return ((const int*)p)[i];
}

// ---------------- dtype detection (int32 vs int64 indices) ----------------
__global__ void detect_kernel(const void* ei, const void* bids, int E, int N) {
    const int* p = (const int*)ei;
    int nz = 0;
    for (int k = 1; k < 129; k += 2) nz += (p[k] != 0);
    g_e64 = (nz <= 4) ? 1 : 0;
    const int* q = (const int*)bids;
    int nz2 = 0;
    int st = N - 63;
    if (!(st & 1)) st++;
    for (int k = st; k < N; k += 2) nz2 += (q[k] != 0);
    g_b64 = (nz2 <= 4) ? 1 : 0;
}

// ---------------- CSR build ----------------
__global__ void zero_kernel() {
    int i = blockIdx.x * blockDim.x + threadIdx.x;
    if (i < NN + 1) g_deg[i] = 0;
    if (i < GG) g_cntg[i] = 0;
}

__global__ void hist_edges_kernel(const void* ei, int E) {
    int e = blockIdx.x * blockDim.x + threadIdx.x;
    if (e >= E) return;
    int is64 = g_e64;
    int dst = ld_idx(ei, (long long)E + e, is64);
    atomicAdd(&g_deg[dst], 1);
}

__global__ void batch_hist_kernel(const void* bids, int N) {
    int tid = blockIdx.x * blockDim.x + threadIdx.x;
    long long i0 = (long long)tid * 8;
    if (i0 >= N) return;
    int is64 = g_b64;
    long long lim = i0 + 8;
    if (lim > N) lim = N;
    int prev = ld_idx(bids, i0, is64);
    int run = 1;
    for (long long i = i0 + 1; i < lim; i++) {
        int b = ld_idx(bids, i, is64);
        if (b == prev)
            run++;
        else {
            atomicAdd(&g_cntg[prev], run);
            prev = b;
            run = 1;
        }
    }
    atomicAdd(&g_cntg[prev], run);
}

__global__ void scan1_kernel(int n) {
    __shared__ int wsum[32];
    int tid = threadIdx.x, lane = tid & 31, wid = tid >> 5;
    int i = blockIdx.x * 1024 + tid;
    int v = (i < n) ? g_deg[i] : 0;
#pragma unroll
    for (int d = 1; d < 32; d <<= 1) {
        int t = __shfl_up_sync(0xffffffffu, v, d);
        if (lane >= d) v += t;
    }
    if (lane == 31) wsum[wid] = v;
    __syncthreads();
    if (wid == 0) {
        int x = wsum[lane];
#pragma unroll
        for (int d = 1; d < 32; d <<= 1) {
            int t = __shfl_up_sync(0xffffffffu, x, d);
            if (lane >= d) x += t;
        }
        wsum[lane] = x;
    }
    __syncthreads();
    if (wid > 0) v += wsum[wid - 1];
    if (i < n) g_row[i + 1] = v;
    if (tid == 1023) g_bsums[blockIdx.x] = wsum[31];
}

// merged: per-block reduction over preceding bsums + apply (no serial scan2)
__global__ void scan23_kernel(int n, int nb) {
    __shared__ int sh[128];
    int t = threadIdx.x;
    if (t < 128) sh[t] = (t < nb && t < blockIdx.x) ? g_bsums[t] : 0;
    __syncthreads();
    for (int s = 64; s > 0; s >>= 1) {
        if (t < s) sh[t] += sh[t + s];
        __syncthreads();
    }
    int off = sh[0];
    int i = blockIdx.x * 1024 + t;
    if (i < n) {
        int val = g_row[i + 1] + off;
        g_row[i + 1] = val;
        g_cur[i + 1] = val;
    }
    if (blockIdx.x == 0 && t == 0) {
        g_row[0] = 0;
        g_cur[0] = 0;
    }
}

__global__ void fill_kernel(const void* ei, int E) {
    int e = blockIdx.x * blockDim.x + threadIdx.x;
    if (e >= E) return;
    int is64 = g_e64;
    int src = ld_idx(ei, e, is64);
    int dst = ld_idx(ei, (long long)E + e, is64);
    int pos = atomicAdd(&g_cur[dst], 1);
    g_src[pos] = src;
}

// ---------------- projection v2: outer-product blocking ----------------
// 256 threads, 32-node tile. thread = (matrix, cg 0..15, ng 0..3);
// accumulates cols 4cg..4cg+3 x nodes 8ng..8ng+7.
// per j: 2 LDS.128 (x, 16-lane broadcast) + 1 LDG.128 (W row chunk, L1-hot) + 16 FFMA2.
template <int FIN>
__global__ void __launch_bounds__(256) proj_kernel(const float* __restrict__ hin,
                                                   const float* __restrict__ Wq, const float* __restrict__ bq,
                                                   const float* __restrict__ Wk, const float* __restrict__ bk,
                                                   const float* __restrict__ Wv, const float* __restrict__ bv,
                                                   const float* __restrict__ Ws, const float* __restrict__ bs,
                                                   int nN) {
    __shared__ __align__(16) float xsh[FIN * 36];  // transposed tile [j][node], stride 36
    int t = threadIdx.x;
    int mat = t >> 6;        // warp-uniform: 0=Q 1=K 2=V 3=S
    int r = t & 63;
    int cg = r & 15;         // column group: cols 4cg..4cg+3
    int ng = r >> 4;         // node group: nodes 8ng..8ng+7
    const float* W;
    const float* B;
    float* O;
    if (mat == 0) { W = Wq; B = bq; O = g_Q; }
    else if (mat == 1) { W = Wk; B = bk; O = g_K; }
    else if (mat == 2) { W = Wv; B = bv; O = g_V; }
    else { W = Ws; B = bs; O = g_S; }

    int base = blockIdx.x * 32;
    int cnt = nN - base;
    if (cnt > 32) cnt = 32;

    // stage x tile (coalesced), zero-fill tail nodes
    for (int idx = t; idx < 32 * FIN; idx += 256) {
        int nd = idx / FIN;
        int j = idx - nd * FIN;
        xsh[j * 36 + nd] = (nd < cnt) ? hin[(long long)base * FIN + idx] : 0.f;
    }
    __syncthreads();

    float4 b4 = *reinterpret_cast<const float4*>(&B[4 * cg]);
    unsigned long long acc[4][4];
#pragma unroll
    for (int k = 0; k < 4; k++) {
        acc[0][k] = pack2(b4.x, b4.x);
        acc[1][k] = pack2(b4.y, b4.y);
        acc[2][k] = pack2(b4.z, b4.z);
        acc[3][k] = pack2(b4.w, b4.w);
    }

#pragma unroll 4
    for (int j = 0; j < FIN; j++) {
        float4 w4 = __ldg(reinterpret_cast<const float4*>(&W[j * 64 + 4 * cg]));
        ulonglong2 x01 = *reinterpret_cast<const ulonglong2*>(&xsh[j * 36 + 8 * ng]);
        ulonglong2 x23 = *reinterpret_cast<const ulonglong2*>(&xsh[j * 36 + 8 * ng + 4]);
        unsigned long long ws;
        ws = pack2(w4.x, w4.x);
        acc[0][0] = ffma2(x01.x, ws, acc[0][0]);
        acc[0][1] = ffma2(x01.y, ws, acc[0][1]);
        acc[0][2] = ffma2(x23.x, ws, acc[0][2]);
        acc[0][3] = ffma2(x23.y, ws, acc[0][3]);
        ws = pack2(w4.y, w4.y);
        acc[1][0] = ffma2(x01.x, ws, acc[1][0]);
        acc[1][1] = ffma2(x01.y, ws, acc[1][1]);
        acc[1][2] = ffma2(x23.x, ws, acc[1][2]);
        acc[1][3] = ffma2(x23.y, ws, acc[1][3]);
        ws = pack2(w4.z, w4.z);
        acc[2][0] = ffma2(x01.x, ws, acc[2][0]);
        acc[2][1] = ffma2(x01.y, ws, acc[2][1]);
        acc[2][2] = ffma2(x23.x, ws, acc[2][2]);
        acc[2][3] = ffma2(x23.y, ws, acc[2][3]);
        ws = pack2(w4.w, w4.w);
        acc[3][0] = ffma2(x01.x, ws, acc[3][0]);
        acc[3][1] = ffma2(x01.y, ws, acc[3][1]);
        acc[3][2] = ffma2(x23.x, ws, acc[3][2]);
        acc[3][3] = ffma2(x23.y, ws, acc[3][3]);
    }

    // store: per node pair k -> two coalesced float4 rows
#pragma unroll
    for (int k = 0; k < 4; k++) {
        float f0l, f0h, f1l, f1h, f2l, f2h, f3l, f3h;
        unpack2(acc[0][k], f0l, f0h);
        unpack2(acc[1][k], f1l, f1h);
        unpack2(acc[2][k], f2l, f2h);
        unpack2(acc[3][k], f3l, f3h);
        int nd = 8 * ng + 2 * k;
        if (nd < cnt) {
            float4 o = {f0l, f1l, f2l, f3l};
            *reinterpret_cast<float4*>(&O[(long long)(base + nd) * 64 + 4 * cg]) = o;
        }
        if (nd + 1 < cnt) {
            float4 o = {f0h, f1h, f2h, f3h};
            *reinterpret_cast<float4*>(&O[(long long)(base + nd + 1) * 64 + 4 * cg]) = o;
        }
    }
}

// ---------------- attention: 2 edges/warp, 16 lanes/edge (R4 known-good) ----------------
__global__ void __launch_bounds__(256) attn_kernel(float* __restrict__ hout, int nN) {
    int node = (blockIdx.x << 3) + (threadIdx.x >> 5);
    if (node >= nN) return;
    int lane = threadIdx.x & 31;
    int sub = lane >> 4;   // which edge of the pair
    int sl = lane & 15;    // dim group: dims 4sl..4sl+3
    float4 q4 = *reinterpret_cast<const float4*>(&g_Q[(long long)node * 64 + 4 * sl]);
    int start = g_row[node], end = g_row[node + 1];
    float m = -1e30f, s = 0.f;
    float4 a = {0.f, 0.f, 0.f, 0.f};
    for (int e = start; e < end; e += 2) {
        int ee = e + sub;
        bool act = ee < end;
        int cur = act ? __ldg(&g_src[ee]) : 0;
        float4 k4 = *reinterpret_cast<const float4*>(&g_K[(long long)cur * 64 + 4 * sl]);
        float4 v4 = *reinterpret_cast<const float4*>(&g_V[(long long)cur * 64 + 4 * sl]);
        float pdot = q4.x * k4.x + q4.y * k4.y + q4.z * k4.z + q4.w * k4.w;
#pragma unroll
        for (int off = 8; off; off >>= 1) pdot += __shfl_xor_sync(0xffffffffu, pdot, off);
        pdot *= 0.125f;  // 1/sqrt(64)
        if (!act) pdot = -1e30f;
        float mn = fmaxf(m, pdot);
        float cs = __expf(m - mn);
        float w = act ? __expf(pdot - mn) : 0.f;
        s = s * cs + w;
        a.x = a.x * cs + w * v4.x;
        a.y = a.y * cs + w * v4.y;
        a.z = a.z * cs + w * v4.z;
        a.w = a.w * cs + w * v4.w;
        m = mn;
    }
    // merge the two half-warp softmax streams (exact in fp32)
    float m2 = __shfl_xor_sync(0xffffffffu, m, 16);
    float s2 = __shfl_xor_sync(0xffffffffu, s, 16);
    float bx = __shfl_xor_sync(0xffffffffu, a.x, 16);
    float by = __shfl_xor_sync(0xffffffffu, a.y, 16);
    float bz = __shfl_xor_sync(0xffffffffu, a.z, 16);
    float bw = __shfl_xor_sync(0xffffffffu, a.w, 16);
    float M = fmaxf(m, m2);
    float c1 = __expf(m - M);
    float c2 = __expf(m2 - M);
    s = s * c1 + s2 * c2;
    a.x = a.x * c1 + bx * c2;
    a.y = a.y * c1 + by * c2;
    a.z = a.z * c1 + bz * c2;
    a.w = a.w * c1 + bw * c2;
    float inv = 1.f / (s + 1e-16f);
    if (sub == 0) {
        float4 sk = *reinterpret_cast<const float4*>(&g_S[(long long)node * 64 + 4 * sl]);
        float4 o;
        o.x = a.x * inv + sk.x;
        o.y = a.y * inv + sk.y;
        o.z = a.z * inv + sk.z;
        o.w = a.w * inv + sk.w;
        *reinterpret_cast<float4*>(&hout[(long long)node * 64 + 4 * sl]) = o;
    }
}

// ---------------- mean pool per graph + final linear ----------------
__global__ void __launch_bounds__(256) pool_kernel(const float* __restrict__ h,
                                                   const float* __restrict__ Wf,
                                                   const float* __restrict__ bf,
                                                   float* __restrict__ out) {
    __shared__ int ired[256];
    __shared__ float fred[256];
    __shared__ float pooled[64];
    int g = blockIdx.x, t = threadIdx.x;
    ired[t] = (t < g) ? g_cntg[t] : 0;
    __syncthreads();
    for (int sft = 128; sft > 0; sft >>= 1) {
        if (t < sft) ired[t] += ired[t + sft];
        __syncthreads();
    }
    int start = ired[0];
    int cntv = g_cntg[g];
    int dim = t & 63, qd = t >> 6;
    float loc = 0.f;
    for (int i = start + qd; i < start + cntv; i += 4) loc += h[(long long)i * 64 + dim];
    fred[t] = loc;
    __syncthreads();
    if (t < 64)
        pooled[t] = (fred[t] + fred[t + 64] + fred[t + 128] + fred[t + 192]) /
                    fmaxf((float)cntv, 1.f);
    __syncthreads();
    if (t < 5) {
        float acc = bf[t];
#pragma unroll
        for (int d = 0; d < 64; d++) acc += pooled[d] * Wf[d * 5 + t];
        out[g * 5 + t] = acc;
    }
}

// ---------------- launch ----------------
extern "C" void kernel_launch(void* const* d_in, const int* in_sizes, int n_in,
                              void* d_out, int out_size) {
    const float* x = (const float*)d_in[0];
    const void* ei = d_in[1];
    const void* bids = d_in[2];
    const float* Wq0 = (const float*)d_in[3];
    const float* bq0 = (const float*)d_in[4];
    const float* Wk0 = (const float*)d_in[5];
    const float* bk0 = (const float*)d_in[6];
    const float* Wv0 = (const float*)d_in[7];
    const float* bv0 = (const float*)d_in[8];
    const float* Ws0 = (const float*)d_in[9];
    const float* bs0 = (const float*)d_in[10];
    const float* Wqh = (const float*)d_in[11];
    const float* bqh = (const float*)d_in[12];
    const float* Wkh = (const float*)d_in[13];
    const float* bkh = (const float*)d_in[14];
    const float* Wvh = (const float*)d_in[15];
    const float* bvh = (const float*)d_in[16];
    const float* Wsh = (const float*)d_in[17];
    const float* bsh = (const float*)d_in[18];
    const float* Wf = (const float*)d_in[19];
    const float* bf = (const float*)d_in[20];
    float* out = (float*)d_out;

    int N = in_sizes[0] / 16;  // 100000
    int E = in_sizes[1] / 2;   // 1200000

    float *h1, *h2;
    cudaGetSymbolAddress((void**)&h1, g_h1);
    cudaGetSymbolAddress((void**)&h2, g_h2);

    int proj_grid = (N + 31) / 32;
    int attn_grid = (N + 7) / 8;
    int nb1 = (N + 1023) / 1024;

    // prep; proj<16> kept at launch slot 4 (ncu capture slot, measurement target)
    detect_kernel<<<1, 1>>>(ei, bids, E, N);
    zero_kernel<<<(NN + 256) / 256, 256>>>();
    hist_edges_kernel<<<(E + 255) / 256, 256>>>(ei, E);
    proj_kernel<16><<<proj_grid, 256>>>(x, Wq0, bq0, Wk0, bk0, Wv0, bv0, Ws0, bs0, N);
    scan1_kernel<<<nb1, 1024>>>(N);
    scan23_kernel<<<nb1, 1024>>>(N, nb1);
    fill_kernel<<<(E + 255) / 256, 256>>>(ei, E);
    batch_hist_kernel<<<((N + 7) / 8 + 255) / 256, 256>>>(bids, N);

    // layer 0 aggregation
    attn_kernel<<<attn_grid, 256>>>(h1, N);

    // hidden layers
    const float* hin = h1;
    float* hout = h2;
    for (int i = 0; i < 3; i++) {
        proj_kernel<64><<<proj_grid, 256>>>(hin, Wqh + (size_t)i * 4096, bqh + (size_t)i * 64,
                                            Wkh + (size_t)i * 4096, bkh + (size_t)i * 64,
                                            Wvh + (size_t)i * 4096, bvh + (size_t)i * 64,
                                            Wsh + (size_t)i * 4096, bsh + (size_t)i * 64, N);
        attn_kernel<<<attn_grid, 256>>>(hout, N);
        const float* tmp = hin;
        hin = hout;
        hout = (float*)tmp;
    }

    // pool + head
    pool_kernel<<<GG, 256>>>(hin, Wf, bf, out);
}